// round 5
// baseline (speedup 1.0000x reference)
#include <cuda_runtime.h>
#include <cuda_bf16.h>
#include <cstdint>

// BinaryConv2d via mma.sync (HMMA) implicit GEMM, bf16 hi/lo split, fp32 accum.
// out[n,o,h,w] = sum_{c,kh,kw} x[n,c,h+kh-1,w+kw-1]*sign(W[o,c,kh,kw]) + bias[o]

#define NB 32
#define CI 128
#define CO 256
#define HH 56
#define HP 58
#define PIXN (HH*HH)          // 3136
#define NPIX (NB*PIXN)        // 100352
#define KTOT 2304             // 9 taps * 256 (hi128 + lo128)
#define NITER 36              // K-chunks of 64

// padded NHWC bf16, channel = [hi(128), lo(128)]
__device__ __nv_bfloat16 g_xp[(size_t)NB*HP*HP*256];
// binarized weights [oc][k], k = tap*256 + cc (cc<128: hi-c, cc>=128: lo-c, same sign)
__device__ __nv_bfloat16 g_wb[(size_t)CO*KTOT];

// ---------------- transforms ----------------
__global__ __launch_bounds__(256)
void transform_x_kernel(const float* __restrict__ x) {
    __shared__ float s[128][57];
    const int hp = blockIdx.x % HP;
    const int n  = blockIdx.x / HP;
    const int tid = threadIdx.x;
    const bool interior_h = (hp >= 1 && hp <= HH);

    if (interior_h) {
        const int h = hp - 1;
        const float* src = x + ((size_t)n * CI * HH + h) * HH;
        for (int idx = tid; idx < CI * HH; idx += 256) {
            int c = idx / HH, w = idx - (idx / HH) * HH;
            s[c][w] = src[(size_t)c * PIXN + w];
        }
    }
    __syncthreads();

    const int c = tid & 127;
    const int half = tid >> 7;          // 0 = hi, 1 = lo
    __nv_bfloat16* ob = g_xp + ((size_t)(n * HP + hp) * HP) * 256 + half * 128 + c;
#pragma unroll 2
    for (int wp = 0; wp < HP; wp++) {
        float v = 0.0f;
        if (interior_h && wp >= 1 && wp <= HH) v = s[c][wp - 1];
        __nv_bfloat16 hi = __float2bfloat16_rn(v);
        __nv_bfloat16 o = half ? __float2bfloat16_rn(v - __bfloat162float(hi)) : hi;
        ob[(size_t)wp * 256] = o;
    }
}

__global__ void transform_w_kernel(const float* __restrict__ w) {
    int idx = blockIdx.x * blockDim.x + threadIdx.x;   // over CO*KTOT
    if (idx >= CO * KTOT) return;
    int oc = idx / KTOT;
    int k  = idx - oc * KTOT;
    int tap = k >> 8;
    int c   = k & 127;        // hi and lo planes share the sign
    float v = w[((size_t)oc * CI + c) * 9 + tap];
    g_wb[idx] = __float2bfloat16_rn(v >= 0.0f ? 1.0f : -1.0f);
}

// ---------------- main kernel ----------------
__device__ __forceinline__ uint32_t smem_u32(const void* p) {
    uint32_t a;
    asm("{ .reg .u64 t; cvta.to.shared.u64 t, %1; cvt.u32.u64 %0, t; }" : "=r"(a) : "l"(p));
    return a;
}
__device__ __forceinline__ void cp16(uint32_t dst, const void* src) {
    asm volatile("cp.async.cg.shared.global [%0], [%1], 16;" :: "r"(dst), "l"(src));
}
#define CP_COMMIT() asm volatile("cp.async.commit_group;" ::: "memory")
#define CP_WAIT1()  asm volatile("cp.async.wait_group 1;" ::: "memory")

__device__ __forceinline__ void ldsm4(uint32_t* r, uint32_t addr) {
    asm volatile("ldmatrix.sync.aligned.m8n8.x4.shared.b16 {%0,%1,%2,%3}, [%4];"
        : "=r"(r[0]), "=r"(r[1]), "=r"(r[2]), "=r"(r[3]) : "r"(addr));
}
__device__ __forceinline__ void mma16816(float* c, const uint32_t* a, uint32_t b0, uint32_t b1) {
    asm volatile("mma.sync.aligned.m16n8k16.row.col.f32.bf16.bf16.f32 "
        "{%0,%1,%2,%3}, {%4,%5,%6,%7}, {%8,%9}, {%0,%1,%2,%3};"
        : "+f"(c[0]), "+f"(c[1]), "+f"(c[2]), "+f"(c[3])
        : "r"(a[0]), "r"(a[1]), "r"(a[2]), "r"(a[3]), "r"(b0), "r"(b1));
}

#define STAGES 3
#define A_ST  16384                 // 128 pix x 64 k x bf16
#define B_ST  16384                 // 128 oc  x 64 k x bf16
#define ST_BYTES (A_ST + B_ST)      // 32 KB / stage
#define SMEM_SZ (STAGES * ST_BYTES) // 96 KB -> 2 CTAs/SM

__global__ __launch_bounds__(256, 2)
void binconv_hmma_kernel(const float* __restrict__ bias, float* __restrict__ out) {
    extern __shared__ char smem[];
    const uint32_t sb = smem_u32(smem);

    const int tid  = threadIdx.x;
    const int wid  = tid >> 5;
    const int lane = tid & 31;
    const int q0     = blockIdx.x * 128;
    const int ocbase = blockIdx.y * 128;

    // ---- producer addressing ----
    // A: 1024 16B-units/stage: unit u -> pixel=u>>3, seg=u&7 (k_local = seg*8)
    size_t xrow[4];
    uint32_t adst[4];
#pragma unroll
    for (int j = 0; j < 4; j++) {
        int u = tid + j * 256;
        int pix = u >> 3, seg = u & 7;
        int q  = q0 + pix;
        int n_ = q / PIXN;
        int r_ = q - n_ * PIXN;
        int h_ = r_ / HH;
        int w_ = r_ - h_ * HH;
        xrow[j] = ((size_t)(n_ * HP + h_) * HP + w_) * 256 + seg * 8;
        adst[j] = sb + (uint32_t)(seg * 128 + pix) * 16;
    }
    // B: 1024 units/stage: unit u -> oc_local=u>>3, seg=u&7
    size_t bsrc[4];
    uint32_t bdst[4];
#pragma unroll
    for (int j = 0; j < 4; j++) {
        int u = tid + j * 256;
        int ocl = u >> 3, seg = u & 7;
        bsrc[j] = (size_t)(ocbase + ocl) * KTOT + seg * 8;
        bdst[j] = sb + A_ST + (uint32_t)(seg * 128 + ocl) * 16;
    }

    // warp tiling: 4 (M) x 2 (N); warp tile 32 x 64
    const int wm = (wid & 3) * 32;
    const int wn = (wid >> 2) * 64;

    float acc[2][8][4];
#pragma unroll
    for (int mi = 0; mi < 2; mi++)
#pragma unroll
        for (int nb = 0; nb < 8; nb++)
#pragma unroll
            for (int j = 0; j < 4; j++) acc[mi][nb][j] = 0.0f;

    auto issue = [&](int it) {
        const uint32_t soff = (uint32_t)(it % STAGES) * ST_BYTES;
        const int tap = it >> 2;
        const int sub = it & 3;
        const int dh = tap / 3, dw = tap - dh * 3;
        const size_t aoff = ((size_t)dh * HP + dw) * 256 + sub * 64;
#pragma unroll
        for (int j = 0; j < 4; j++)
            cp16(adst[j] + soff, g_xp + xrow[j] + aoff);
        const size_t boff = (size_t)it * 64;
#pragma unroll
        for (int j = 0; j < 4; j++)
            cp16(bdst[j] + soff, g_wb + bsrc[j] + boff);
        CP_COMMIT();
    };

    issue(0);
    issue(1);

    // ldmatrix lane addressing (within a k16 block); seg stride = 128*16 = 2048
    const uint32_t a_lrow = (uint32_t)((lane >> 4) * 128 + (lane & 15)) * 16;
    const uint32_t b_lrow = (uint32_t)(((lane >> 3) & 1) * 128 + (lane & 7) + ((lane >> 4) << 3)) * 16;

    for (int it = 0; it < NITER; it++) {
        const uint32_t soff = (uint32_t)(it % STAGES) * ST_BYTES;
        CP_WAIT1();
        __syncthreads();
        if (it + 2 < NITER) issue(it + 2);
        else CP_COMMIT();   // keep group count consistent so WAIT1 covers the real tail

#pragma unroll
        for (int kb = 0; kb < 4; kb++) {
            uint32_t af[2][4], bf[4][4];
#pragma unroll
            for (int mi = 0; mi < 2; mi++)
                ldsm4(af[mi], sb + soff + kb * 4096 + a_lrow + (uint32_t)(wm + mi * 16) * 16);
#pragma unroll
            for (int nj = 0; nj < 4; nj++)
                ldsm4(bf[nj], sb + A_ST + soff + kb * 4096 + b_lrow + (uint32_t)(wn + nj * 16) * 16);
#pragma unroll
            for (int mi = 0; mi < 2; mi++)
#pragma unroll
                for (int nb = 0; nb < 8; nb++) {
                    const uint32_t* bp = bf[nb >> 1];
                    if (nb & 1) mma16816(acc[mi][nb], af[mi], bp[2], bp[3]);
                    else        mma16816(acc[mi][nb], af[mi], bp[0], bp[1]);
                }
        }
    }

    // ---------------- epilogue: fused bias, coalesced NCHW stores ----------------
    const int qr  = lane >> 2;           // 0..7 (pixel within 8)
    const int oc2 = (lane & 3) * 2;      // oc pair offset

    float2 bv[8];
#pragma unroll
    for (int nb = 0; nb < 8; nb++)
        bv[nb] = *(const float2*)(bias + ocbase + wn + nb * 8 + oc2);

#pragma unroll
    for (int mi = 0; mi < 2; mi++) {
#pragma unroll
        for (int half = 0; half < 2; half++) {
            const int p  = q0 + wm + mi * 16 + half * 8 + qr;   // global pixel
            const int n2 = p / PIXN;
            const int rm = p - n2 * PIXN;
            float* ob = out + (size_t)n2 * CO * PIXN + rm;
#pragma unroll
            for (int nb = 0; nb < 8; nb++) {
                const int oc = ocbase + wn + nb * 8 + oc2;
                ob[(size_t)oc * PIXN]       = acc[mi][nb][half * 2 + 0] + bv[nb].x;
                ob[(size_t)(oc + 1) * PIXN] = acc[mi][nb][half * 2 + 1] + bv[nb].y;
            }
        }
    }
}

// ---------------- launch ----------------
extern "C" void kernel_launch(void* const* d_in, const int* in_sizes, int n_in,
                              void* d_out, int out_size) {
    const float* x      = (const float*)d_in[0];
    const float* weight = (const float*)d_in[1];
    const float* bias   = (const float*)d_in[2];
    float* out          = (float*)d_out;

    cudaFuncSetAttribute(binconv_hmma_kernel,
                         cudaFuncAttributeMaxDynamicSharedMemorySize, SMEM_SZ);

    transform_x_kernel<<<NB * HP, 256>>>(x);
    {
        int total = CO * KTOT;
        transform_w_kernel<<<(total + 255) / 256, 256>>>(weight);
    }
    dim3 grid(NPIX / 128, 2);
    binconv_hmma_kernel<<<grid, 256, SMEM_SZ>>>(bias, out);
}

// round 6
// speedup vs baseline: 2.7825x; 2.7825x over previous
#include <cuda_runtime.h>
#include <cuda_fp16.h>
#include <cstdint>

// BinaryConv2d via mma.sync (HMMA) implicit GEMM, fp16 inputs, fp32 accum.
// out[n,o,h,w] = sum_{c,kh,kw} x[n,c,h+kh-1,w+kw-1]*sign(W[o,c,kh,kw]) + bias[o]
// Precision: x quantized once to fp16 (rel rms ~2.8e-4), weights ±1 exact in fp16.

#define NB 32
#define CI 128
#define CO 256
#define HH 56
#define HP 58
#define PIXN (HH*HH)          // 3136
#define NPIX (NB*PIXN)        // 100352
#define KTOT 1152             // 9 taps * 128 channels
#define NITER 18              // K-chunks of 64

// padded NHWC fp16
__device__ __half g_xp[(size_t)NB*HP*HP*128];
// binarized weights [oc][k], k = tap*128 + c
__device__ __half g_wb[(size_t)CO*KTOT];

// ---------------- transforms ----------------
__global__ __launch_bounds__(256)
void transform_x_kernel(const float* __restrict__ x) {
    __shared__ float s[128][57];
    const int hp = blockIdx.x % HP;
    const int n  = blockIdx.x / HP;
    const int tid = threadIdx.x;
    const bool interior_h = (hp >= 1 && hp <= HH);

    if (interior_h) {
        const int h = hp - 1;
        const float* src = x + ((size_t)n * CI * HH + h) * HH;
        for (int idx = tid; idx < CI * HH; idx += 256) {
            int c = idx / HH, w = idx - (idx / HH) * HH;
            s[c][w] = src[(size_t)c * PIXN + w];
        }
    }
    __syncthreads();

    const int c  = tid & 127;
    const int wh = tid >> 7;             // wp half: 0 -> [0,29), 1 -> [29,58)
    __half* ob = g_xp + ((size_t)(n * HP + hp) * HP) * 128 + c;
#pragma unroll 4
    for (int wp = wh * 29; wp < wh * 29 + 29; wp++) {
        float v = 0.0f;
        if (interior_h && wp >= 1 && wp <= HH) v = s[c][wp - 1];
        ob[(size_t)wp * 128] = __float2half_rn(v);
    }
}

__global__ void transform_w_kernel(const float* __restrict__ w) {
    int idx = blockIdx.x * blockDim.x + threadIdx.x;   // over CO*KTOT
    if (idx >= CO * KTOT) return;
    int oc = idx / KTOT;
    int k  = idx - oc * KTOT;
    int tap = k >> 7;
    int c   = k & 127;
    float v = w[((size_t)oc * CI + c) * 9 + tap];
    g_wb[idx] = __float2half_rn(v >= 0.0f ? 1.0f : -1.0f);
}

// ---------------- main kernel ----------------
__device__ __forceinline__ uint32_t smem_u32(const void* p) {
    uint32_t a;
    asm("{ .reg .u64 t; cvta.to.shared.u64 t, %1; cvt.u32.u64 %0, t; }" : "=r"(a) : "l"(p));
    return a;
}
__device__ __forceinline__ void cp16(uint32_t dst, const void* src) {
    asm volatile("cp.async.cg.shared.global [%0], [%1], 16;" :: "r"(dst), "l"(src));
}
#define CP_COMMIT() asm volatile("cp.async.commit_group;" ::: "memory")
#define CP_WAIT1()  asm volatile("cp.async.wait_group 1;" ::: "memory")

__device__ __forceinline__ void ldsm4(uint32_t* r, uint32_t addr) {
    asm volatile("ldmatrix.sync.aligned.m8n8.x4.shared.b16 {%0,%1,%2,%3}, [%4];"
        : "=r"(r[0]), "=r"(r[1]), "=r"(r[2]), "=r"(r[3]) : "r"(addr));
}
__device__ __forceinline__ void mma16816(float* c, const uint32_t* a, uint32_t b0, uint32_t b1) {
    asm volatile("mma.sync.aligned.m16n8k16.row.col.f32.f16.f16.f32 "
        "{%0,%1,%2,%3}, {%4,%5,%6,%7}, {%8,%9}, {%0,%1,%2,%3};"
        : "+f"(c[0]), "+f"(c[1]), "+f"(c[2]), "+f"(c[3])
        : "r"(a[0]), "r"(a[1]), "r"(a[2]), "r"(a[3]), "r"(b0), "r"(b1));
}

#define STAGES 3
#define A_ST  16384                 // 128 pix x 64 k x fp16
#define B_ST  32768                 // 256 oc  x 64 k x fp16
#define ST_BYTES (A_ST + B_ST)      // 48 KB / stage
#define SMEM_SZ (STAGES * ST_BYTES) // 144 KB

__global__ __launch_bounds__(512, 1)
void binconv_hmma_kernel(const float* __restrict__ bias, float* __restrict__ out) {
    extern __shared__ char smem[];
    const uint32_t sb = smem_u32(smem);

    const int tid  = threadIdx.x;
    const int wid  = tid >> 5;
    const int lane = tid & 31;
    const int q0   = blockIdx.x * 128;

    // ---- producer addressing ----
    // A: 1024 16B-units/stage: unit u -> pixel=u>>3, seg=u&7 (k_local = seg*8)
    size_t xrow[2];
    uint32_t adst[2];
#pragma unroll
    for (int j = 0; j < 2; j++) {
        int u = tid + j * 512;
        int pix = u >> 3, seg = u & 7;
        int q  = q0 + pix;
        int n_ = q / PIXN;
        int r_ = q - n_ * PIXN;
        int h_ = r_ / HH;
        int w_ = r_ - h_ * HH;
        xrow[j] = ((size_t)(n_ * HP + h_) * HP + w_) * 128 + seg * 8;
        adst[j] = sb + (uint32_t)(seg * 128 + pix) * 16;
    }
    // B: 2048 units/stage: unit u -> oc=u>>3, seg=u&7
    size_t bsrc[4];
    uint32_t bdst[4];
#pragma unroll
    for (int j = 0; j < 4; j++) {
        int u = tid + j * 512;
        int oc = u >> 3, seg = u & 7;
        bsrc[j] = (size_t)oc * KTOT + seg * 8;
        bdst[j] = sb + A_ST + (uint32_t)(seg * 256 + oc) * 16;
    }

    // warp tiling: 4 (M) x 4 (N); warp tile 32 x 64
    const int wm = (wid & 3) * 32;
    const int wn = (wid >> 2) * 64;

    float acc[2][8][4];
#pragma unroll
    for (int mi = 0; mi < 2; mi++)
#pragma unroll
        for (int nb = 0; nb < 8; nb++)
#pragma unroll
            for (int j = 0; j < 4; j++) acc[mi][nb][j] = 0.0f;

    auto issue = [&](int it) {
        const uint32_t soff = (uint32_t)(it % STAGES) * ST_BYTES;
        const int tap = it >> 1;            // 2 chunks of 64 per tap (tap = 128 k)
        const int sub = it & 1;
        const int dh = tap / 3, dw = tap - dh * 3;
        const size_t aoff = ((size_t)dh * HP + dw) * 128 + sub * 64;
#pragma unroll
        for (int j = 0; j < 2; j++)
            cp16(adst[j] + soff, g_xp + xrow[j] + aoff);
        const size_t boff = (size_t)it * 64;
#pragma unroll
        for (int j = 0; j < 4; j++)
            cp16(bdst[j] + soff, g_wb + bsrc[j] + boff);
        CP_COMMIT();
    };

    issue(0);
    issue(1);

    // ldmatrix lane addressing (within a k16 block)
    const uint32_t a_lrow = (uint32_t)((lane >> 4) * 128 + (lane & 15)) * 16;
    const uint32_t b_lrow = (uint32_t)(((lane >> 3) & 1) * 256 + (lane & 7) + ((lane >> 4) << 3)) * 16;

    for (int it = 0; it < NITER; it++) {
        const uint32_t soff = (uint32_t)(it % STAGES) * ST_BYTES;
        CP_WAIT1();
        __syncthreads();
        if (it + 2 < NITER) issue(it + 2);
        else CP_COMMIT();   // keep group count consistent so WAIT1 covers the real tail

#pragma unroll
        for (int kb = 0; kb < 4; kb++) {
            uint32_t af[2][4], bf[4][4];
#pragma unroll
            for (int mi = 0; mi < 2; mi++)
                ldsm4(af[mi], sb + soff + kb * 4096 + a_lrow + (uint32_t)(wm + mi * 16) * 16);
#pragma unroll
            for (int nj = 0; nj < 4; nj++)
                ldsm4(bf[nj], sb + A_ST + soff + kb * 8192 + b_lrow + (uint32_t)(wn + nj * 16) * 16);
#pragma unroll
            for (int mi = 0; mi < 2; mi++)
#pragma unroll
                for (int nb = 0; nb < 8; nb++) {
                    const uint32_t* bp = bf[nb >> 1];
                    if (nb & 1) mma16816(acc[mi][nb], af[mi], bp[2], bp[3]);
                    else        mma16816(acc[mi][nb], af[mi], bp[0], bp[1]);
                }
        }
    }

    // ---------------- epilogue: fused bias, coalesced NCHW stores ----------------
    const int qr  = lane >> 2;           // 0..7 (pixel within 8)
    const int oc2 = (lane & 3) * 2;      // oc pair offset

    float2 bv[8];
#pragma unroll
    for (int nb = 0; nb < 8; nb++)
        bv[nb] = *(const float2*)(bias + wn + nb * 8 + oc2);

#pragma unroll
    for (int mi = 0; mi < 2; mi++) {
#pragma unroll
        for (int half = 0; half < 2; half++) {
            const int p  = q0 + wm + mi * 16 + half * 8 + qr;   // global pixel
            const int n2 = p / PIXN;
            const int rm = p - n2 * PIXN;
            float* ob = out + (size_t)n2 * CO * PIXN + rm;
#pragma unroll
            for (int nb = 0; nb < 8; nb++) {
                const int oc = wn + nb * 8 + oc2;
                ob[(size_t)oc * PIXN]       = acc[mi][nb][half * 2 + 0] + bv[nb].x;
                ob[(size_t)(oc + 1) * PIXN] = acc[mi][nb][half * 2 + 1] + bv[nb].y;
            }
        }
    }
}

// ---------------- launch ----------------
extern "C" void kernel_launch(void* const* d_in, const int* in_sizes, int n_in,
                              void* d_out, int out_size) {
    const float* x      = (const float*)d_in[0];
    const float* weight = (const float*)d_in[1];
    const float* bias   = (const float*)d_in[2];
    float* out          = (float*)d_out;

    cudaFuncSetAttribute(binconv_hmma_kernel,
                         cudaFuncAttributeMaxDynamicSharedMemorySize, SMEM_SZ);

    transform_x_kernel<<<NB * HP, 256>>>(x);
    {
        int total = CO * KTOT;
        transform_w_kernel<<<(total + 255) / 256, 256>>>(weight);
    }
    binconv_hmma_kernel<<<NPIX / 128, 512, SMEM_SZ>>>(bias, out);
}